// round 1
// baseline (speedup 1.0000x reference)
#include <cuda_runtime.h>
#include <math.h>
#include <stdint.h>

// Problem constants
#define BB 64
#define LL 128
#define EE 300
#define HH 256
#define G4 1024           // 4*H
#define NEV 34
#define NAR 36
#define MM (BB*LL)        // 8192
#define KF 512            // 2*H

// ---------------- scratch (device globals; no allocation allowed) ----------------
__device__ float d_emb[MM*EE];                 // [8192,300]
__device__ float d_xg[2][MM*G4];               // per-dir gate preactivations
__device__ float d_hs[MM*KF];                  // [8192,512] concat hidden states
__device__ float d_hbuf[2][2][BB*HH];          // double-buffered h per dir
__device__ float d_base[MM*NAR];               // hs @ argW_hs^T + arg_b
__device__ float d_tc[MM*NAR];                 // hs @ argW_trig^T
__device__ int   d_evpred[MM];
__device__ float d_wcol[68*NAR];               // transposed carry-feature weight cols
__device__ int   d_cnt[2][4][130];             // per-(dir,bquarter) step arrival counters

// ---------------- K1: embedding gather + flag reset + wcol transpose ----------------
__global__ void k_embed(const int* __restrict__ ids,
                        const float* __restrict__ table,
                        const float* __restrict__ arg_w) {
    int tid = blockIdx.x * blockDim.x + threadIdx.x;
    if (tid < 2*4*130) ((int*)d_cnt)[tid] = 0;
    if (tid < 68*NAR) {
        int c = tid / NAR, a = tid % NAR;
        d_wcol[c*NAR + a] = arg_w[a*1092 + 1024 + c];
    }
    int total = MM*EE;
    int stride = gridDim.x * blockDim.x;
    for (int i = tid; i < total; i += stride) {
        int m = i / EE, e = i - m*EE;
        d_emb[i] = table[(long long)ids[m]*EE + e];
    }
}

// ---------------- K2: xg = emb @ w_ih^T + b  (NT sgemm, 128x128x16 tiles) ----------------
__global__ void __launch_bounds__(256) k_xg_gemm(const float* __restrict__ w_f,
                                                 const float* __restrict__ b_f,
                                                 const float* __restrict__ w_b,
                                                 const float* __restrict__ b_b) {
    int dir = blockIdx.z;
    const float* W    = dir ? w_b : w_f;
    const float* bias = dir ? b_b : b_f;
    float* C = d_xg[dir];

    __shared__ __align__(16) float As[16][132];
    __shared__ __align__(16) float Bs[16][132];

    int m0 = blockIdx.y * 128;
    int n0 = blockIdx.x * 128;
    int t  = threadIdx.x;
    int tm = (t / 16) * 8;
    int tn = (t % 16) * 8;

    float acc[8][8];
    #pragma unroll
    for (int i = 0; i < 8; i++)
        #pragma unroll
        for (int j = 0; j < 8; j++) acc[i][j] = 0.f;

    for (int k0 = 0; k0 < EE; k0 += 16) {
        #pragma unroll
        for (int i = 0; i < 8; i++) {
            int idx = t + i*256;            // 0..2047
            int row = idx >> 4, kk = idx & 15;
            int k = k0 + kk;
            As[kk][row] = (k < EE) ? d_emb[(m0+row)*EE + k] : 0.f;
            Bs[kk][row] = (k < EE) ? W[(n0+row)*EE + k]     : 0.f;
        }
        __syncthreads();
        #pragma unroll
        for (int kk = 0; kk < 16; kk++) {
            float4 a0 = *(const float4*)&As[kk][tm];
            float4 a1 = *(const float4*)&As[kk][tm+4];
            float4 b0 = *(const float4*)&Bs[kk][tn];
            float4 b1 = *(const float4*)&Bs[kk][tn+4];
            float av[8] = {a0.x,a0.y,a0.z,a0.w,a1.x,a1.y,a1.z,a1.w};
            float bv[8] = {b0.x,b0.y,b0.z,b0.w,b1.x,b1.y,b1.z,b1.w};
            #pragma unroll
            for (int i = 0; i < 8; i++)
                #pragma unroll
                for (int j = 0; j < 8; j++)
                    acc[i][j] += av[i]*bv[j];
        }
        __syncthreads();
    }
    float bv[8];
    #pragma unroll
    for (int j = 0; j < 8; j++) bv[j] = bias[n0+tn+j];
    #pragma unroll
    for (int i = 0; i < 8; i++)
        #pragma unroll
        for (int j = 0; j < 8; j++)
            C[(long long)(m0+tm+i)*G4 + n0+tn+j] = acc[i][j] + bv[j];
}

// ---------------- K3: persistent BiLSTM, 256 blocks x 128 threads ----------------
// block = (dir:2) x (u_tile:32 of 8 units) x (bquarter:4 of 16 batch rows)
// thread = (b_local:16) x (u:8); computes all 4 gates for its (b,u); c in register.
__global__ void __launch_bounds__(128) k_lstm(const float* __restrict__ whh_f,
                                              const float* __restrict__ whh_b) {
    int blk = blockIdx.x;
    int dir = blk >> 7;
    int ut  = (blk >> 2) & 31;
    int bq  = blk & 3;

    __shared__ __align__(16) float w_s[4*8*HH];   // 32KB [gate][u][k]
    __shared__ __align__(16) float h_s[16*HH];    // 16KB [b_local][k]

    int t  = threadIdx.x;
    int bl = t >> 3;
    int u  = t & 7;
    int b  = bq*16 + bl;
    int uglob = ut*8 + u;

    const float* whh = dir ? whh_b : whh_f;
    // load constant w tile once
    for (int i = t; i < 4*8*HH; i += 128) {
        int g  = i >> 11;
        int uu = (i >> 8) & 7;
        int k  = i & 255;
        w_s[i] = whh[(g*HH + ut*8 + uu)*HH + k];
    }
    __syncthreads();

    float c = 0.f;
    const float* xg = d_xg[dir];
    volatile int* cnt = &d_cnt[dir][bq][0];

    for (int s = 0; s < LL; s++) {
        if (s == 0) {
            for (int i = t; i < 16*HH; i += 128) h_s[i] = 0.f;
        } else {
            if (t == 0) { while (cnt[s-1] < 32) { } }
            __syncthreads();
            const float* hb = d_hbuf[dir][s & 1];
            for (int i = t; i < 16*HH; i += 128) {
                int bb = i >> 8, k = i & 255;
                h_s[i] = __ldcg(&hb[(bq*16 + bb)*HH + k]);
            }
        }
        __syncthreads();

        float a0=0.f, a1=0.f, a2=0.f, a3=0.f;
        const float4* h4  = (const float4*)&h_s[bl*HH];
        const float4* w04 = (const float4*)&w_s[(0*8+u)*HH];
        const float4* w14 = (const float4*)&w_s[(1*8+u)*HH];
        const float4* w24 = (const float4*)&w_s[(2*8+u)*HH];
        const float4* w34 = (const float4*)&w_s[(3*8+u)*HH];
        #pragma unroll 8
        for (int k4 = 0; k4 < HH/4; k4++) {
            float4 hv = h4[k4];
            float4 q0 = w04[k4], q1 = w14[k4], q2 = w24[k4], q3 = w34[k4];
            a0 += q0.x*hv.x + q0.y*hv.y + q0.z*hv.z + q0.w*hv.w;
            a1 += q1.x*hv.x + q1.y*hv.y + q1.z*hv.z + q1.w*hv.w;
            a2 += q2.x*hv.x + q2.y*hv.y + q2.z*hv.z + q2.w*hv.w;
            a3 += q3.x*hv.x + q3.y*hv.y + q3.z*hv.z + q3.w*hv.w;
        }
        int tpos = dir ? (LL-1-s) : s;
        int m = b*LL + tpos;
        const float* xr = &xg[(long long)m*G4];
        float gi = a0 + xr[uglob];
        float gf = a1 + xr[HH + uglob];
        float gg = a2 + xr[2*HH + uglob];
        float go = a3 + xr[3*HH + uglob];
        float si = 1.f/(1.f + expf(-gi));
        float sf = 1.f/(1.f + expf(-gf));
        float so = 1.f/(1.f + expf(-go));
        c = sf*c + si*tanhf(gg);
        float h = so*tanhf(c);

        d_hbuf[dir][(s+1)&1][b*HH + uglob] = h;
        d_hs[(long long)m*KF + dir*HH + uglob] = h;

        __threadfence();
        __syncthreads();
        if (t == 0) atomicAdd((int*)&d_cnt[dir][bq][s], 1);
    }
}

// ---------------- K4: per-position head precompute (warp per m) ----------------
__global__ void __launch_bounds__(256) k_head(const float* __restrict__ event_w,
                                              const float* __restrict__ event_b,
                                              const float* __restrict__ arg_w,
                                              const float* __restrict__ arg_b,
                                              float* __restrict__ out_ev) {
    int w = (blockIdx.x * blockDim.x + threadIdx.x) >> 5;
    int lane = threadIdx.x & 31;
    if (w >= MM) return;

    float h[16];
    const float* hr = &d_hs[(long long)w*KF];
    #pragma unroll
    for (int r = 0; r < 16; r++) h[r] = hr[r*32 + lane];

    // event logits + argmax (first max)
    float best = -INFINITY; int bi = 0;
    for (int e = 0; e < NEV; e++) {
        const float* wr = &event_w[e*KF];
        float acc = 0.f;
        #pragma unroll
        for (int r = 0; r < 16; r++) acc += h[r]*wr[r*32 + lane];
        #pragma unroll
        for (int off = 16; off; off >>= 1) acc += __shfl_xor_sync(0xffffffffu, acc, off);
        acc += event_b[e];
        if (lane == 0) out_ev[(long long)w*NEV + e] = acc;
        if (acc > best) { best = acc; bi = e; }
    }
    if (lane == 0) d_evpred[w] = bi;

    // trig contribution (arg_w cols 512..1023)
    for (int a = 0; a < NAR; a++) {
        const float* wr = &arg_w[a*1092 + 512];
        float acc = 0.f;
        #pragma unroll
        for (int r = 0; r < 16; r++) acc += h[r]*wr[r*32 + lane];
        #pragma unroll
        for (int off = 16; off; off >>= 1) acc += __shfl_xor_sync(0xffffffffu, acc, off);
        if (lane == 0) d_tc[(long long)w*NAR + a] = acc;
    }
    // base (arg_w cols 0..511) + bias
    for (int a = 0; a < NAR; a++) {
        const float* wr = &arg_w[a*1092];
        float acc = 0.f;
        #pragma unroll
        for (int r = 0; r < 16; r++) acc += h[r]*wr[r*32 + lane];
        #pragma unroll
        for (int off = 16; off; off >>= 1) acc += __shfl_xor_sync(0xffffffffu, acc, off);
        if (lane == 0) d_base[(long long)w*NAR + a] = acc + arg_b[a];
    }
}

// ---------------- K5: trigger scan, warp per (b,j), carry in registers ----------------
__global__ void __launch_bounds__(256) k_scan(float* __restrict__ out_arg) {
    int gw = (blockIdx.x * blockDim.x + threadIdx.x) >> 5;
    int lane = threadIdx.x & 31;
    if (gw >= MM) return;
    int b = gw >> 7, j = gw & 127;

    float bas0 = d_base[(long long)gw*NAR + lane];
    float bas1 = (lane < 4) ? d_base[(long long)gw*NAR + 32 + lane] : 0.f;
    float ext0 = 0.f, ext1 = 0.f;
    unsigned long long maskA = 0ull, maskT = 0ull;
    const int* evp_row = &d_evpred[b*LL];

    for (int i = 0; i < LL; i++) {
        int mrow = b*LL + i;
        float tc0 = d_tc[(long long)mrow*NAR + lane];
        float tc1 = (lane < 4) ? d_tc[(long long)mrow*NAR + 32 + lane] : 0.f;
        int ev = evp_row[i];

        float l0 = bas0 + ext0 + tc0;
        float l1 = bas1 + ext1 + tc1;

        long long o = ((long long)mrow*LL + j) * NAR;
        out_arg[o + lane] = l0;
        if (lane < 4) out_arg[o + 32 + lane] = l1;

        // argmax over 36 (ties -> lowest index, matching jnp.argmax)
        float v = l0; int idx = lane;
        if (lane < 4 && l1 > v) { v = l1; idx = lane + 32; }
        #pragma unroll
        for (int off = 16; off; off >>= 1) {
            float ov = __shfl_xor_sync(0xffffffffu, v, off);
            int   oi = __shfl_xor_sync(0xffffffffu, idx, off);
            if (ov > v || (ov == v && oi < idx)) { v = ov; idx = oi; }
        }

        if (ev > 0 && idx > 0) {
            unsigned bA = (unsigned)(idx - 1);          // 0..34
            if (!((maskA >> bA) & 1ull)) {
                maskA |= (1ull << bA);
                ext0 += d_wcol[bA*NAR + lane];
                if (lane < 4) ext1 += d_wcol[bA*NAR + 32 + lane];
            }
            unsigned bT = (unsigned)(ev - 1);           // 0..32
            if (!((maskT >> bT) & 1ull)) {
                maskT |= (1ull << bT);
                int cc = 35 + (int)bT;
                ext0 += d_wcol[cc*NAR + lane];
                if (lane < 4) ext1 += d_wcol[cc*NAR + 32 + lane];
            }
        }
    }
}

// ---------------- launch ----------------
extern "C" void kernel_launch(void* const* d_in, const int* in_sizes, int n_in,
                              void* d_out, int out_size) {
    const int*   ids      = (const int*)  d_in[0];
    const float* emb_tab  = (const float*)d_in[1];
    const float* w_ih_f   = (const float*)d_in[2];
    const float* w_hh_f   = (const float*)d_in[3];
    const float* b_f      = (const float*)d_in[4];
    const float* w_ih_b   = (const float*)d_in[5];
    const float* w_hh_b   = (const float*)d_in[6];
    const float* b_b      = (const float*)d_in[7];
    const float* event_w  = (const float*)d_in[8];
    const float* event_b  = (const float*)d_in[9];
    const float* arg_w    = (const float*)d_in[10];
    const float* arg_b    = (const float*)d_in[11];

    float* out_ev  = (float*)d_out;                       // [B,L,NE]
    float* out_arg = out_ev + (long long)MM*NEV;          // [B,L,L,NA]

    k_embed<<<2048, 256>>>(ids, emb_tab, arg_w);
    k_xg_gemm<<<dim3(G4/128, MM/128, 2), 256>>>(w_ih_f, b_f, w_ih_b, b_b);
    k_lstm<<<256, 128>>>(w_hh_f, w_hh_b);
    k_head<<<MM/8, 256>>>(event_w, event_b, arg_w, arg_b, out_ev);
    k_scan<<<MM/8, 256>>>(out_arg);
}

// round 2
// speedup vs baseline: 3.2812x; 3.2812x over previous
#include <cuda_runtime.h>
#include <math.h>
#include <stdint.h>

// Problem constants
#define BB 64
#define LL 128
#define EE 300
#define HH 256
#define G4 1024           // 4*H
#define NEV 34
#define NAR 36
#define MM (BB*LL)        // 8192
#define KF 512            // 2*H
#define NC 106            // concat head rows: 34 ev + 36 trig + 36 base

// ---------------- scratch (device globals; no allocation allowed) ----------------
__device__ float d_emb[MM*EE];                 // [8192,300]
__device__ float d_xg[2][MM*G4];               // per-dir gate preactivations
__device__ float d_hs[MM*KF];                  // [8192,512] concat hidden states
__device__ float d_hbuf[2][2][BB*HH];          // double-buffered h per dir
__device__ float d_base[MM*NAR];               // hs @ argW_hs^T + arg_b
__device__ float d_tc[MM*NAR];                 // hs @ argW_trig^T
__device__ int   d_evpred[MM];
__device__ float d_wcol[68*NAR];               // transposed carry-feature weight cols
__device__ float d_wcat[NC*KF];                // concat head weights [106,512]
__device__ int   d_cnt[2][4][130];             // per-(dir,bquarter) step arrival counters

// ---------------- sync helpers ----------------
__device__ __forceinline__ void red_release(int* p) {
    asm volatile("red.release.gpu.global.add.s32 [%0], %1;" :: "l"(p), "r"(1) : "memory");
}
__device__ __forceinline__ int ld_acquire(const int* p) {
    int v;
    asm volatile("ld.acquire.gpu.global.s32 %0, [%1];" : "=r"(v) : "l"(p) : "memory");
    return v;
}

// ---------------- K1: gather + flag reset + wcol/wcat staging ----------------
__global__ void k_embed(const int* __restrict__ ids,
                        const float* __restrict__ table,
                        const float* __restrict__ arg_w,
                        const float* __restrict__ event_w) {
    int tid = blockIdx.x * blockDim.x + threadIdx.x;
    int stride = gridDim.x * blockDim.x;
    if (tid < 2*4*130) ((int*)d_cnt)[tid] = 0;
    if (tid < 68*NAR) {
        int c = tid / NAR, a = tid % NAR;
        d_wcol[c*NAR + a] = arg_w[a*1092 + 1024 + c];
    }
    for (int i = tid; i < NC*KF; i += stride) {
        int n = i >> 9, k = i & 511;
        float v;
        if (n < 34)      v = event_w[n*KF + k];
        else if (n < 70) v = arg_w[(n-34)*1092 + 512 + k];
        else             v = arg_w[(n-70)*1092 + k];
        d_wcat[i] = v;
    }
    int total = MM*EE;
    for (int i = tid; i < total; i += stride) {
        int m = i / EE, e = i - m*EE;
        d_emb[i] = table[(long long)ids[m]*EE + e];
    }
}

// ---------------- K2: xg = emb @ w_ih^T + b  (NT sgemm, 128x128x16 tiles) ----------------
__global__ void __launch_bounds__(256) k_xg_gemm(const float* __restrict__ w_f,
                                                 const float* __restrict__ b_f,
                                                 const float* __restrict__ w_b,
                                                 const float* __restrict__ b_b) {
    int dir = blockIdx.z;
    const float* W    = dir ? w_b : w_f;
    const float* bias = dir ? b_b : b_f;
    float* C = d_xg[dir];

    __shared__ __align__(16) float As[16][132];
    __shared__ __align__(16) float Bs[16][132];

    int m0 = blockIdx.y * 128;
    int n0 = blockIdx.x * 128;
    int t  = threadIdx.x;
    int tm = (t / 16) * 8;
    int tn = (t % 16) * 8;

    float acc[8][8];
    #pragma unroll
    for (int i = 0; i < 8; i++)
        #pragma unroll
        for (int j = 0; j < 8; j++) acc[i][j] = 0.f;

    for (int k0 = 0; k0 < EE; k0 += 16) {
        #pragma unroll
        for (int i = 0; i < 8; i++) {
            int idx = t + i*256;
            int row = idx >> 4, kk = idx & 15;
            int k = k0 + kk;
            As[kk][row] = (k < EE) ? d_emb[(m0+row)*EE + k] : 0.f;
            Bs[kk][row] = (k < EE) ? W[(n0+row)*EE + k]     : 0.f;
        }
        __syncthreads();
        #pragma unroll
        for (int kk = 0; kk < 16; kk++) {
            float4 a0 = *(const float4*)&As[kk][tm];
            float4 a1 = *(const float4*)&As[kk][tm+4];
            float4 b0 = *(const float4*)&Bs[kk][tn];
            float4 b1 = *(const float4*)&Bs[kk][tn+4];
            float av[8] = {a0.x,a0.y,a0.z,a0.w,a1.x,a1.y,a1.z,a1.w};
            float bv[8] = {b0.x,b0.y,b0.z,b0.w,b1.x,b1.y,b1.z,b1.w};
            #pragma unroll
            for (int i = 0; i < 8; i++)
                #pragma unroll
                for (int j = 0; j < 8; j++)
                    acc[i][j] += av[i]*bv[j];
        }
        __syncthreads();
    }
    float bv[8];
    #pragma unroll
    for (int j = 0; j < 8; j++) bv[j] = bias[n0+tn+j];
    #pragma unroll
    for (int i = 0; i < 8; i++)
        #pragma unroll
        for (int j = 0; j < 8; j++)
            C[(long long)(m0+tm+i)*G4 + n0+tn+j] = acc[i][j] + bv[j];
}

// ---------------- K3: persistent BiLSTM, 256 blocks x 128 threads ----------------
// block = (dir:2) x (u_tile:32 of 8 units) x (bquarter:4 of 16 batch rows)
// Conflict-free smem: w as [k4][gate][u] float4; h XOR-swizzled [k4][bl^k4].
__global__ void __launch_bounds__(128) k_lstm(const float* __restrict__ whh_f,
                                              const float* __restrict__ whh_b) {
    int blk = blockIdx.x;
    int dir = blk >> 7;
    int ut  = (blk >> 2) & 31;
    int bq  = blk & 3;

    __shared__ __align__(16) float4 w4[64*4*8];    // 32KB: [k4][g][u]
    __shared__ __align__(16) float4 h4s[64*16];    // 16KB: [k4][bl^(k4&15)]
    float* wsf = (float*)w4;
    float* hsf = (float*)h4s;

    int t  = threadIdx.x;
    int bl = t >> 3;
    int u  = t & 7;
    int b  = bq*16 + bl;
    int uglob = ut*8 + u;

    const float* whh = dir ? whh_b : whh_f;
    for (int i = t; i < 4*8*HH; i += 128) {
        int g  = i >> 11;
        int uu = (i >> 8) & 7;
        int k  = i & 255;
        float v = whh[(g*HH + ut*8 + uu)*HH + k];
        wsf[(((k>>2)*4 + g)*8 + uu)*4 + (k&3)] = v;
    }
    __syncthreads();

    float c = 0.f;
    const float* xg = d_xg[dir];
    int* cnt = &d_cnt[dir][bq][0];

    for (int s = 0; s < LL; s++) {
        if (s == 0) {
            for (int i = t; i < 16*HH; i += 128) hsf[i] = 0.f;
        } else {
            if (t == 0) { while (ld_acquire(&cnt[s-1]) < 32) { } }
            __syncthreads();
            const float* hb = d_hbuf[dir][s & 1];
            for (int i = t; i < 16*HH; i += 128) {
                int bb = i >> 8, k = i & 255;
                float v = __ldcg(&hb[(bq*16 + bb)*HH + k]);
                int k4 = k >> 2;
                hsf[(k4*16 + (bb ^ (k4 & 15)))*4 + (k & 3)] = v;
            }
        }
        __syncthreads();

        // prefetch xg row
        int tpos = dir ? (LL-1-s) : s;
        int m = b*LL + tpos;
        const float* xr = &xg[(long long)m*G4];
        float x0 = xr[uglob];
        float x1 = xr[HH + uglob];
        float x2 = xr[2*HH + uglob];
        float x3 = xr[3*HH + uglob];

        float a0=0.f, a1=0.f, a2=0.f, a3=0.f;
        #pragma unroll 8
        for (int k4 = 0; k4 < 64; k4++) {
            float4 hv = h4s[(k4<<4) + (bl ^ (k4 & 15))];
            float4 q0 = w4[((k4<<2)+0)*8 + u];
            float4 q1 = w4[((k4<<2)+1)*8 + u];
            float4 q2 = w4[((k4<<2)+2)*8 + u];
            float4 q3 = w4[((k4<<2)+3)*8 + u];
            a0 += q0.x*hv.x + q0.y*hv.y + q0.z*hv.z + q0.w*hv.w;
            a1 += q1.x*hv.x + q1.y*hv.y + q1.z*hv.z + q1.w*hv.w;
            a2 += q2.x*hv.x + q2.y*hv.y + q2.z*hv.z + q2.w*hv.w;
            a3 += q3.x*hv.x + q3.y*hv.y + q3.z*hv.z + q3.w*hv.w;
        }
        float gi = a0 + x0;
        float gf = a1 + x1;
        float gg = a2 + x2;
        float go = a3 + x3;
        float si = 1.f/(1.f + expf(-gi));
        float sf = 1.f/(1.f + expf(-gf));
        float so = 1.f/(1.f + expf(-go));
        c = sf*c + si*tanhf(gg);
        float h = so*tanhf(c);

        __stcg(&d_hbuf[dir][(s+1)&1][b*HH + uglob], h);
        d_hs[(long long)m*KF + dir*HH + uglob] = h;

        __syncthreads();
        if (t == 0) red_release(&cnt[s]);
    }
}

// ---------------- K4: head GEMM (64m x 106n x 512k) with fused epilogue ----------------
// acc = hs[64,512] @ d_wcat^T -> [64,106]; then ev argmax + base/tc staging.
__global__ void __launch_bounds__(256) k_head(const float* __restrict__ event_b,
                                              const float* __restrict__ arg_b,
                                              float* __restrict__ out_ev) {
    __shared__ __align__(16) float As[64][68];    // [kk][m]  17.4KB
    __shared__ __align__(16) float Bs[64][116];   // [kk][n]  29.7KB

    int t = threadIdx.x;
    int m0 = blockIdx.x * 64;
    int tm = (t >> 4) * 4;      // 0..60
    int tn = (t & 15) * 7;      // 0..105

    float acc[4][7];
    #pragma unroll
    for (int i = 0; i < 4; i++)
        #pragma unroll
        for (int j = 0; j < 7; j++) acc[i][j] = 0.f;

    for (int k0 = 0; k0 < KF; k0 += 64) {
        for (int idx = t; idx < 64*64; idx += 256) {
            int kk = idx & 63, mi = idx >> 6;
            As[kk][mi] = d_hs[(long long)(m0+mi)*KF + k0 + kk];
        }
        for (int idx = t; idx < NC*64; idx += 256) {
            int kk = idx & 63, n = idx >> 6;
            Bs[kk][n] = d_wcat[n*KF + k0 + kk];
        }
        __syncthreads();
        #pragma unroll 4
        for (int kk = 0; kk < 64; kk++) {
            float4 a4 = *(const float4*)&As[kk][tm];
            float av[4] = {a4.x, a4.y, a4.z, a4.w};
            #pragma unroll
            for (int j = 0; j < 7; j++) {
                float bv = Bs[kk][tn+j];
                #pragma unroll
                for (int i = 0; i < 4; i++) acc[i][j] += av[i]*bv;
            }
        }
        __syncthreads();
    }

    // stash logits into Bs region: lg[m][n] stride 116
    float* lg = &Bs[0][0];
    #pragma unroll
    for (int i = 0; i < 4; i++)
        #pragma unroll
        for (int j = 0; j < 7; j++)
            lg[(tm+i)*116 + tn+j] = acc[i][j];
    __syncthreads();

    int wid = t >> 5, lane = t & 31;
    for (int mm = wid; mm < 64; mm += 8) {
        int m = m0 + mm;
        const float* lr = &lg[mm*116];
        // event logits + argmax (34)
        float v = -INFINITY; int idx = 0;
        if (lane < 34) { v = lr[lane] + event_b[lane]; idx = lane; }
        if (lane < 2) {
            float v2 = lr[32+lane] + event_b[32+lane];
            if (lane < 34) { /* both valid */ }
            if (v2 > v) { v = v2; idx = 32+lane; }
        }
        if (lane < 34) out_ev[(long long)m*NEV + lane] = lr[lane] + event_b[lane];
        if (lane < 2)  out_ev[(long long)m*NEV + 32 + lane] = lr[32+lane] + event_b[32+lane];
        #pragma unroll
        for (int off = 16; off; off >>= 1) {
            float ov = __shfl_xor_sync(0xffffffffu, v, off);
            int   oi = __shfl_xor_sync(0xffffffffu, idx, off);
            if (ov > v || (ov == v && oi < idx)) { v = ov; idx = oi; }
        }
        if (lane == 0) d_evpred[m] = idx;
        // trig contribution rows 34..69
        d_tc[(long long)m*NAR + lane] = lr[34 + lane];
        if (lane < 4) d_tc[(long long)m*NAR + 32 + lane] = lr[66 + lane];
        // base rows 70..105 (+ bias)
        d_base[(long long)m*NAR + lane] = lr[70 + lane] + arg_b[lane];
        if (lane < 4) d_base[(long long)m*NAR + 32 + lane] = lr[102 + lane] + arg_b[32 + lane];
    }
}

// ---------------- K5: trigger scan, warp per (b,j), carry in registers ----------------
__global__ void __launch_bounds__(256) k_scan(float* __restrict__ out_arg) {
    int gw = (blockIdx.x * blockDim.x + threadIdx.x) >> 5;
    int lane = threadIdx.x & 31;
    if (gw >= MM) return;
    int b = gw >> 7, j = gw & 127;

    float bas0 = d_base[(long long)gw*NAR + lane];
    float bas1 = (lane < 4) ? d_base[(long long)gw*NAR + 32 + lane] : 0.f;
    float ext0 = 0.f, ext1 = 0.f;
    unsigned long long maskA = 0ull, maskT = 0ull;
    const int* evp_row = &d_evpred[b*LL];

    for (int i = 0; i < LL; i++) {
        int mrow = b*LL + i;
        float tc0 = d_tc[(long long)mrow*NAR + lane];
        float tc1 = (lane < 4) ? d_tc[(long long)mrow*NAR + 32 + lane] : 0.f;
        int ev = evp_row[i];

        float l0 = bas0 + ext0 + tc0;
        float l1 = bas1 + ext1 + tc1;

        long long o = ((long long)mrow*LL + j) * NAR;
        out_arg[o + lane] = l0;
        if (lane < 4) out_arg[o + 32 + lane] = l1;

        float v = l0; int idx = lane;
        if (lane < 4 && l1 > v) { v = l1; idx = lane + 32; }
        #pragma unroll
        for (int off = 16; off; off >>= 1) {
            float ov = __shfl_xor_sync(0xffffffffu, v, off);
            int   oi = __shfl_xor_sync(0xffffffffu, idx, off);
            if (ov > v || (ov == v && oi < idx)) { v = ov; idx = oi; }
        }

        if (ev > 0 && idx > 0) {
            unsigned bA = (unsigned)(idx - 1);
            if (!((maskA >> bA) & 1ull)) {
                maskA |= (1ull << bA);
                ext0 += d_wcol[bA*NAR + lane];
                if (lane < 4) ext1 += d_wcol[bA*NAR + 32 + lane];
            }
            unsigned bT = (unsigned)(ev - 1);
            if (!((maskT >> bT) & 1ull)) {
                maskT |= (1ull << bT);
                int cc = 35 + (int)bT;
                ext0 += d_wcol[cc*NAR + lane];
                if (lane < 4) ext1 += d_wcol[cc*NAR + 32 + lane];
            }
        }
    }
}

// ---------------- launch ----------------
extern "C" void kernel_launch(void* const* d_in, const int* in_sizes, int n_in,
                              void* d_out, int out_size) {
    const int*   ids      = (const int*)  d_in[0];
    const float* emb_tab  = (const float*)d_in[1];
    const float* w_ih_f   = (const float*)d_in[2];
    const float* w_hh_f   = (const float*)d_in[3];
    const float* b_f      = (const float*)d_in[4];
    const float* w_ih_b   = (const float*)d_in[5];
    const float* w_hh_b   = (const float*)d_in[6];
    const float* b_b      = (const float*)d_in[7];
    const float* event_w  = (const float*)d_in[8];
    const float* event_b  = (const float*)d_in[9];
    const float* arg_w    = (const float*)d_in[10];
    const float* arg_b    = (const float*)d_in[11];

    float* out_ev  = (float*)d_out;                       // [B,L,NE]
    float* out_arg = out_ev + (long long)MM*NEV;          // [B,L,L,NA]

    k_embed<<<2048, 256>>>(ids, emb_tab, arg_w, event_w);
    k_xg_gemm<<<dim3(G4/128, MM/128, 2), 256>>>(w_ih_f, b_f, w_ih_b, b_b);
    k_lstm<<<256, 128>>>(w_hh_f, w_hh_b);
    k_head<<<MM/64, 256>>>(event_b, arg_b, out_ev);
    k_scan<<<MM/8, 256>>>(out_arg);
}